// round 7
// baseline (speedup 1.0000x reference)
#include <cuda_runtime.h>
#include <cuda.h>
#include <cuda_bf16.h>
#include <cstdint>

// Shapes (fixed): B=4, S=2048, D=1024
#define BB 4
#define SS 2048
#define DD 1024
#define MQKV (BB * SS)            // 8192

// ---- GEMM tile: 256x128 block, BK=32 (64B rows, SW64), 8 warps, 4 stages ---
#define TM_ 256
#define TN_ 128
#define BK 32
#define A_TILE_B (256 * 64)       // 16384
#define B_TILE_B (128 * 64)       // 8192
#define STAGE_B  (2 * A_TILE_B + 2 * B_TILE_B)   // 49152
#define NSTAGE 4
#define SMEM_TOTAL (1024 + NSTAGE * STAGE_B)     // 197632
#define NT 256                    // 8 warps

// ---------------- scratch (device globals; allocation-free rule) -----------
__device__ __align__(256) __nv_bfloat16 g_xh[(size_t)MQKV * DD];
__device__ __align__(256) __nv_bfloat16 g_xl[(size_t)MQKV * DD];
__device__ __align__(256) __nv_bfloat16 g_Wth[3][(size_t)DD * DD];   // W^T hi (Q,K,V)
__device__ __align__(256) __nv_bfloat16 g_Wtl[3][(size_t)DD * DD];   // W^T lo
__device__ __align__(256) float         g_F[(size_t)MQKV * DD];      // fp32 staging (V)
__device__ __align__(256) __nv_bfloat16 g_QKh[2][(size_t)MQKV * DD]; // Q,K hi planes
__device__ __align__(256) __nv_bfloat16 g_QKl[2][(size_t)MQKV * DD]; // Q,K lo planes
__device__ __align__(256) __nv_bfloat16 g_Vth[(size_t)DD * MQKV];    // V^T [D, B*S]
__device__ __align__(256) __nv_bfloat16 g_Vtl[(size_t)DD * MQKV];
__device__ __align__(256) __nv_bfloat16 g_Ph[(size_t)BB * SS * SS];  // exp(S) hi
__device__ __align__(256) __nv_bfloat16 g_Pl[(size_t)BB * SS * SS];  // exp(S) lo
__device__ __align__(256) float         g_RS[MQKV];                  // row sums

// ---------------- PTX helpers ----------------------------------------------
__device__ __forceinline__ uint32_t smem_u32(const void* p) {
    uint32_t a;
    asm("{ .reg .u64 t; cvta.to.shared.u64 t, %1; cvt.u32.u64 %0, t; }"
        : "=r"(a) : "l"(p));
    return a;
}
#define LDSM4(r, addr)                                                      \
    asm volatile("ldmatrix.sync.aligned.m8n8.x4.shared.b16 {%0,%1,%2,%3}, [%4];" \
        : "=r"((r)[0]), "=r"((r)[1]), "=r"((r)[2]), "=r"((r)[3]) : "r"(addr))

#define MMA(c, a, b0, b1)                                                   \
    asm volatile("mma.sync.aligned.m16n8k16.row.col.f32.bf16.bf16.f32 "     \
        "{%0,%1,%2,%3}, {%4,%5,%6,%7}, {%8,%9}, {%0,%1,%2,%3};"             \
        : "+f"((c)[0]), "+f"((c)[1]), "+f"((c)[2]), "+f"((c)[3])            \
        : "r"((a)[0]), "r"((a)[1]), "r"((a)[2]), "r"((a)[3]),               \
          "r"(b0), "r"(b1))

__device__ __forceinline__ void tma2d(uint32_t dst, const void* map,
                                      int x, int y, uint32_t mb) {
    asm volatile(
        "cp.async.bulk.tensor.2d.shared::cta.global.tile.mbarrier::complete_tx::bytes "
        "[%0], [%1, {%2, %3}], [%4];"
        :: "r"(dst), "l"(map), "r"(x), "r"(y), "r"(mb) : "memory");
}
#define MB_INIT(mb, c) \
    asm volatile("mbarrier.init.shared.b64 [%0], %1;" :: "r"(mb), "r"(c) : "memory")
#define MB_EXPECT(mb, bytes) \
    asm volatile("mbarrier.arrive.expect_tx.shared.b64 _, [%0], %1;" \
                 :: "r"(mb), "r"(bytes) : "memory")
#define MB_WAIT(mb, ph) do {                                               \
    asm volatile("{\n\t.reg .pred P;\n\t"                                  \
        "WL%=:\n\t"                                                        \
        "mbarrier.try_wait.parity.acquire.cta.shared::cta.b64 P, [%0], %1;\n\t" \
        "@!P bra WL%=;\n\t}"                                               \
        :: "r"(mb), "r"(ph) : "memory");                                   \
} while (0)

// ---------------------------------------------------------------------------
// Split-bf16 HMMA GEMM with deep TMA pipeline (4 stages, SW64, BK=32).
//   acc[M,N] = (Ah+Al)[M,K] @ (Bh+Bl)[N,K]^T   (3-term split, fp32 acc)
// EPI=1 (projections, z in {0,1,2}):
//        z<2 : split-bf16 write to Chi/Clo + z*strideC
//        z==2: fp32 write to C (staging for V)
// EPI=2 (scores): p = expf(acc*alpha); split-bf16 write to Chi/Clo + z*strideC
// EPI=3 (AV):     o = acc / RS[z*SS + row]; fp32 write to C + z*strideC
// Grid (N/128, M/256, z). 256 threads, 8 warps of 64x64.
// ---------------------------------------------------------------------------
template <int EPI>
__global__ __launch_bounds__(NT, 1)
void mma_gemm(const __grid_constant__ CUtensorMap mAh,
              const __grid_constant__ CUtensorMap mAl,
              const __grid_constant__ CUtensorMap mBh,
              const __grid_constant__ CUtensorMap mBl,
              float* __restrict__ C,
              __nv_bfloat16* __restrict__ Chi, __nv_bfloat16* __restrict__ Clo,
              const float* __restrict__ RS,
              int K, int ldc, size_t strideC,
              int zRowA, int zRowB, int zColB, float alpha)
{
    extern __shared__ char smem[];
    const uint32_t sbase = smem_u32(smem);
    const uint32_t bufs  = (sbase + 1023u) & ~1023u;   // 1024-align
    const uint32_t mbar  = sbase;                      // 4 mbarriers
    const int tid  = threadIdx.x;
    const int lane = tid & 31, wid = tid >> 5;
    const int bz = blockIdx.z;
    const int tileM = blockIdx.y * TM_;
    const int tileN = blockIdx.x * TN_;
    const int rowA0 = tileM + bz * zRowA;
    const int rowB0 = tileN + bz * zRowB;
    const int colB0 = bz * zColB;

    if (tid == 0) {
        #pragma unroll
        for (int i = 0; i < NSTAGE; i++) MB_INIT(mbar + 8 * i, 1);
    }
    __syncthreads();

    const int nst = K / BK;
    auto issue = [&](int s) {
        const uint32_t buf = bufs + (uint32_t)(s & (NSTAGE - 1)) * STAGE_B;
        const uint32_t mb  = mbar + (uint32_t)(s & (NSTAGE - 1)) * 8;
        const int kt = s * BK;
        MB_EXPECT(mb, STAGE_B);
        tma2d(buf,                           &mAh, kt,         rowA0, mb);
        tma2d(buf + A_TILE_B,                &mAl, kt,         rowA0, mb);
        tma2d(buf + 2 * A_TILE_B,            &mBh, kt + colB0, rowB0, mb);
        tma2d(buf + 2 * A_TILE_B + B_TILE_B, &mBl, kt + colB0, rowB0, mb);
    };
    if (tid == 0) { issue(0); issue(1); issue(2); }

    const int wm = (wid >> 1) * 64;        // warp M offset (0..192)
    const int wn = (wid & 1) * 64;         // warp N offset (0/64)

    // ldmatrix lane addressing; SW64: xor = ((row>>1)&3)<<4 on byte column
    uint32_t aoff[4], axor[4], boff[4], bxor[4];
    {
        const int arl = wm + (lane & 15);
        const int brl = wn + (lane & 7) + ((lane >> 4) * 8);
        #pragma unroll
        for (int i = 0; i < 4; i++) {
            int ar = arl + i * 16;
            aoff[i] = (uint32_t)(ar * 64);
            axor[i] = (uint32_t)(((ar >> 1) & 3) << 4);
            int br = brl + i * 16;
            boff[i] = (uint32_t)(br * 64);
            bxor[i] = (uint32_t)(((br >> 1) & 3) << 4);
        }
    }
    const uint32_t a_colb = (uint32_t)((lane >> 4) * 16);
    const uint32_t b_colb = (uint32_t)(((lane >> 3) & 1) * 16);

    float acc[4][8][4];
    #pragma unroll
    for (int i = 0; i < 4; i++)
        #pragma unroll
        for (int j = 0; j < 8; j++)
            #pragma unroll
            for (int r = 0; r < 4; r++) acc[i][j][r] = 0.0f;

    for (int s = 0; s < nst; s++) {
        const uint32_t buf = bufs + (uint32_t)(s & (NSTAGE - 1)) * STAGE_B;
        MB_WAIT(mbar + (uint32_t)(s & (NSTAGE - 1)) * 8, (uint32_t)((s >> 2) & 1));
        if (tid == 0 && s + 3 < nst) issue(s + 3);   // keep 3 stages in flight

        const uint32_t bufA = buf;
        const uint32_t bufB = buf + 2 * A_TILE_B;
        #pragma unroll
        for (int ks = 0; ks < 2; ks++) {
            const uint32_t kb = (uint32_t)(ks * 32);
            uint32_t ah[4][4], al[4][4], bh[4][4], bl[4][4];
            #pragma unroll
            for (int mt = 0; mt < 4; mt++) {
                uint32_t ra = bufA + aoff[mt] + ((kb + a_colb) ^ axor[mt]);
                LDSM4(ah[mt], ra);
                LDSM4(al[mt], ra + A_TILE_B);
            }
            #pragma unroll
            for (int j = 0; j < 4; j++) {
                uint32_t rb = bufB + boff[j] + ((kb + b_colb) ^ bxor[j]);
                LDSM4(bh[j], rb);
                LDSM4(bl[j], rb + B_TILE_B);
            }
            #pragma unroll
            for (int mt = 0; mt < 4; mt++) {
                #pragma unroll
                for (int j = 0; j < 4; j++) {
                    MMA(acc[mt][2 * j],     ah[mt], bh[j][0], bh[j][1]);
                    MMA(acc[mt][2 * j + 1], ah[mt], bh[j][2], bh[j][3]);
                    MMA(acc[mt][2 * j],     ah[mt], bl[j][0], bl[j][1]);
                    MMA(acc[mt][2 * j + 1], ah[mt], bl[j][2], bl[j][3]);
                    MMA(acc[mt][2 * j],     al[mt], bh[j][0], bh[j][1]);
                    MMA(acc[mt][2 * j + 1], al[mt], bh[j][2], bh[j][3]);
                }
            }
        }
        __syncthreads();
    }

    // ---- epilogue ----
    const int er = lane >> 2;              // 0..7
    const int ec = (lane & 3) * 2;         // 0,2,4,6
    const bool fp32_path = (EPI == 3) || (EPI == 1 && bz == 2);
    float* Cz = C;
    if (EPI == 3) Cz = C + (size_t)bz * strideC;
    __nv_bfloat16* ChiZ = Chi;  __nv_bfloat16* CloZ = Clo;
    if (EPI == 1 || EPI == 2) {
        ChiZ = Chi + (size_t)bz * strideC;
        CloZ = Clo + (size_t)bz * strideC;
    }
    const float* rs = (EPI == 3) ? (RS + (size_t)bz * SS) : nullptr;

    #pragma unroll
    for (int mt = 0; mt < 4; mt++) {
        const int rloc = tileM + wm + mt * 16 + er;
        float inv0 = 0.f, inv1 = 0.f;
        if (EPI == 3) { inv0 = 1.0f / rs[rloc]; inv1 = 1.0f / rs[rloc + 8]; }
        #pragma unroll
        for (int j = 0; j < 8; j++) {
            const int col = tileN + wn + j * 8 + ec;
            float v0 = acc[mt][j][0] * alpha, v1 = acc[mt][j][1] * alpha;
            float v2 = acc[mt][j][2] * alpha, v3 = acc[mt][j][3] * alpha;
            if (EPI == 2) {
                v0 = __expf(v0); v1 = __expf(v1);
                v2 = __expf(v2); v3 = __expf(v3);
            }
            if (EPI == 3) { v0 *= inv0; v1 *= inv0; v2 *= inv1; v3 *= inv1; }
            if (fp32_path) {
                *reinterpret_cast<float2*>(&Cz[(size_t)rloc * ldc + col]) =
                    make_float2(v0, v1);
                *reinterpret_cast<float2*>(&Cz[(size_t)(rloc + 8) * ldc + col]) =
                    make_float2(v2, v3);
            } else {
                __nv_bfloat162 h0, l0, h1, l1;
                h0.x = __float2bfloat16(v0);  h0.y = __float2bfloat16(v1);
                l0.x = __float2bfloat16(v0 - __bfloat162float(h0.x));
                l0.y = __float2bfloat16(v1 - __bfloat162float(h0.y));
                h1.x = __float2bfloat16(v2);  h1.y = __float2bfloat16(v3);
                l1.x = __float2bfloat16(v2 - __bfloat162float(h1.x));
                l1.y = __float2bfloat16(v3 - __bfloat162float(h1.y));
                size_t o0 = (size_t)rloc * ldc + col;
                size_t o1 = (size_t)(rloc + 8) * ldc + col;
                *reinterpret_cast<__nv_bfloat162*>(&ChiZ[o0]) = h0;
                *reinterpret_cast<__nv_bfloat162*>(&CloZ[o0]) = l0;
                *reinterpret_cast<__nv_bfloat162*>(&ChiZ[o1]) = h1;
                *reinterpret_cast<__nv_bfloat162*>(&CloZ[o1]) = l1;
            }
        }
    }
}

// ---------------------------------------------------------------------------
// fp32 -> (hi, lo) bf16 split, elementwise
// ---------------------------------------------------------------------------
__global__ __launch_bounds__(256)
void split_kernel(const float* __restrict__ in,
                  __nv_bfloat16* __restrict__ hi, __nv_bfloat16* __restrict__ lo,
                  size_t n4)
{
    size_t i = (size_t)blockIdx.x * blockDim.x + threadIdx.x;
    if (i >= n4) return;
    float4 v = reinterpret_cast<const float4*>(in)[i];
    __nv_bfloat16 h0 = __float2bfloat16(v.x), h1 = __float2bfloat16(v.y);
    __nv_bfloat16 h2 = __float2bfloat16(v.z), h3 = __float2bfloat16(v.w);
    __nv_bfloat162 hA; hA.x = h0; hA.y = h1;
    __nv_bfloat162 hB; hB.x = h2; hB.y = h3;
    __nv_bfloat162 lA, lB;
    lA.x = __float2bfloat16(v.x - __bfloat162float(h0));
    lA.y = __float2bfloat16(v.y - __bfloat162float(h1));
    lB.x = __float2bfloat16(v.z - __bfloat162float(h2));
    lB.y = __float2bfloat16(v.w - __bfloat162float(h3));
    reinterpret_cast<__nv_bfloat162*>(hi)[2 * i]     = hA;
    reinterpret_cast<__nv_bfloat162*>(hi)[2 * i + 1] = hB;
    reinterpret_cast<__nv_bfloat162*>(lo)[2 * i]     = lA;
    reinterpret_cast<__nv_bfloat162*>(lo)[2 * i + 1] = lB;
}

// ---------------------------------------------------------------------------
// fp32 [R,C] -> transposed (hi, lo) bf16 [C,R]
// ---------------------------------------------------------------------------
__global__ __launch_bounds__(256)
void tsplit_kernel(const float* __restrict__ in,
                   __nv_bfloat16* __restrict__ hi, __nv_bfloat16* __restrict__ lo,
                   int R, int C)
{
    __shared__ float tile[32][33];
    const int c0 = blockIdx.x * 32, r0 = blockIdx.y * 32;
    const int tx = threadIdx.x, ty = threadIdx.y;   // 32 x 8
    #pragma unroll
    for (int j = 0; j < 32; j += 8)
        tile[ty + j][tx] = in[(size_t)(r0 + ty + j) * C + c0 + tx];
    __syncthreads();
    #pragma unroll
    for (int j = 0; j < 32; j += 8) {
        float v = tile[tx][ty + j];
        __nv_bfloat16 h = __float2bfloat16(v);
        size_t o = (size_t)(c0 + ty + j) * R + r0 + tx;
        hi[o] = h;
        lo[o] = __float2bfloat16(v - __bfloat162float(h));
    }
}

// ---------------------------------------------------------------------------
// Row sums of exp(S): RS[row] = sum_j (Ph[row][j] + Pl[row][j])
// ---------------------------------------------------------------------------
__global__ __launch_bounds__(256)
void rowsum_kernel(const __nv_bfloat16* __restrict__ Ph,
                   const __nv_bfloat16* __restrict__ Pl,
                   float* __restrict__ RS)
{
    __shared__ float sh[8];
    const size_t base = (size_t)blockIdx.x * SS;
    const int tid = threadIdx.x;
    const __nv_bfloat162* ph = reinterpret_cast<const __nv_bfloat162*>(Ph + base);
    const __nv_bfloat162* pl = reinterpret_cast<const __nv_bfloat162*>(Pl + base);
    float s = 0.0f;
    #pragma unroll
    for (int i = 0; i < 4; i++) {
        __nv_bfloat162 a = ph[tid + i * 256];
        __nv_bfloat162 b = pl[tid + i * 256];
        s += __bfloat162float(a.x) + __bfloat162float(a.y)
           + __bfloat162float(b.x) + __bfloat162float(b.y);
    }
    #pragma unroll
    for (int o = 16; o > 0; o >>= 1) s += __shfl_xor_sync(~0u, s, o);
    if ((tid & 31) == 0) sh[tid >> 5] = s;
    __syncthreads();
    if (tid < 32) {
        s = (tid < 8) ? sh[tid] : 0.0f;
        #pragma unroll
        for (int o = 4; o > 0; o >>= 1) s += __shfl_xor_sync(~0u, s, o);
        if (tid == 0) RS[blockIdx.x] = s;
    }
}

// ---------------------------------------------------------------------------
// Host: tensor-map builder (driver entry point, no -lcuda needed)
// ---------------------------------------------------------------------------
typedef CUresult (*PFN_TMAPENC)(CUtensorMap*, CUtensorMapDataType, cuuint32_t,
                                void*, const cuuint64_t*, const cuuint64_t*,
                                const cuuint32_t*, const cuuint32_t*,
                                CUtensorMapInterleave, CUtensorMapSwizzle,
                                CUtensorMapL2promotion, CUtensorMapFloatOOBfill);

static void make_map(PFN_TMAPENC enc, CUtensorMap* m, void* base,
                     unsigned long long cols, unsigned long long rows,
                     unsigned box_rows)
{
    cuuint64_t dims[2]    = {cols, rows};
    cuuint64_t strides[1] = {cols * 2};
    cuuint32_t box[2]     = {32, box_rows};     // 32 bf16 = 64B rows
    cuuint32_t es[2]      = {1, 1};
    enc(m, CU_TENSOR_MAP_DATA_TYPE_BFLOAT16, 2, base, dims, strides, box, es,
        CU_TENSOR_MAP_INTERLEAVE_NONE, CU_TENSOR_MAP_SWIZZLE_64B,
        CU_TENSOR_MAP_L2_PROMOTION_L2_128B, CU_TENSOR_MAP_FLOAT_OOB_FILL_NONE);
}

extern "C" void kernel_launch(void* const* d_in, const int* in_sizes, int n_in,
                              void* d_out, int out_size)
{
    const float* x  = (const float*)d_in[0];
    const float* WQ = (const float*)d_in[1];
    const float* WK = (const float*)d_in[2];
    const float* WV = (const float*)d_in[3];
    float* out = (float*)d_out;

    __nv_bfloat16 *xh, *xl, *Wth, *Wtl, *QKh, *QKl, *Vth, *Vtl, *Ph, *Pl;
    float *F, *RS;
    cudaGetSymbolAddress((void**)&xh,  g_xh);
    cudaGetSymbolAddress((void**)&xl,  g_xl);
    cudaGetSymbolAddress((void**)&Wth, g_Wth);
    cudaGetSymbolAddress((void**)&Wtl, g_Wtl);
    cudaGetSymbolAddress((void**)&F,   g_F);
    cudaGetSymbolAddress((void**)&QKh, g_QKh);
    cudaGetSymbolAddress((void**)&QKl, g_QKl);
    cudaGetSymbolAddress((void**)&Vth, g_Vth);
    cudaGetSymbolAddress((void**)&Vtl, g_Vtl);
    cudaGetSymbolAddress((void**)&Ph,  g_Ph);
    cudaGetSymbolAddress((void**)&Pl,  g_Pl);
    cudaGetSymbolAddress((void**)&RS,  g_RS);

    const size_t nQK = (size_t)MQKV * DD;       // plane stride for Q/K
    __nv_bfloat16* Qh = QKh;            __nv_bfloat16* Ql = QKl;
    __nv_bfloat16* Kh = QKh + nQK;      __nv_bfloat16* Kl = QKl + nQK;

    PFN_TMAPENC enc = nullptr;
    cudaDriverEntryPointQueryResult qres;
    cudaGetDriverEntryPoint("cuTensorMapEncodeTiled", (void**)&enc,
                            cudaEnableDefault, &qres);

    const size_t nW = (size_t)DD * DD;
    CUtensorMap mXh, mXl, mWh, mWl, mQh, mQl, mKh, mKl, mPh, mPl, mVh, mVl;
    make_map(enc, &mXh, xh, DD, MQKV, 256);
    make_map(enc, &mXl, xl, DD, MQKV, 256);
    make_map(enc, &mWh, Wth, DD, 3 * DD, 128);   // all 3 weight planes, z-row offset
    make_map(enc, &mWl, Wtl, DD, 3 * DD, 128);
    make_map(enc, &mQh, Qh, DD, MQKV, 256);
    make_map(enc, &mQl, Ql, DD, MQKV, 256);
    make_map(enc, &mKh, Kh, DD, MQKV, 128);
    make_map(enc, &mKl, Kl, DD, MQKV, 128);
    make_map(enc, &mPh, Ph, SS, MQKV, 256);
    make_map(enc, &mPl, Pl, SS, MQKV, 256);
    make_map(enc, &mVh, Vth, MQKV, DD, 128);
    make_map(enc, &mVl, Vtl, MQKV, DD, 128);

    cudaFuncSetAttribute(mma_gemm<1>, cudaFuncAttributeMaxDynamicSharedMemorySize, SMEM_TOTAL);
    cudaFuncSetAttribute(mma_gemm<2>, cudaFuncAttributeMaxDynamicSharedMemorySize, SMEM_TOTAL);
    cudaFuncSetAttribute(mma_gemm<3>, cudaFuncAttributeMaxDynamicSharedMemorySize, SMEM_TOTAL);

    const size_t n4x = (size_t)MQKV * DD / 4;
    dim3 tb(32, 8);

    // 1) input conversions
    split_kernel<<<(unsigned)((n4x + 255) / 256), 256>>>(x, xh, xl, n4x);
    tsplit_kernel<<<dim3(DD / 32, DD / 32), tb>>>(WQ, Wth + 0 * nW, Wtl + 0 * nW, DD, DD);
    tsplit_kernel<<<dim3(DD / 32, DD / 32), tb>>>(WK, Wth + 1 * nW, Wtl + 1 * nW, DD, DD);
    tsplit_kernel<<<dim3(DD / 32, DD / 32), tb>>>(WV, Wth + 2 * nW, Wtl + 2 * nW, DD, DD);

    // 2) all 3 projections in one launch (z: 0=Q split, 1=K split, 2=V fp32)
    dim3 gp(DD / TN_, MQKV / TM_, 3);                 // 8 x 32 x 3
    mma_gemm<1><<<gp, NT, SMEM_TOTAL>>>(mXh, mXl, mWh, mWl,
                                        F, QKh, QKl, nullptr,
                                        DD, DD, nQK, 0, DD, 0, 1.0f);
    tsplit_kernel<<<dim3(DD / 32, MQKV / 32), tb>>>(F, Vth, Vtl, MQKV, DD);

    // 3) scores + exp fused: P = exp(Q @ K^T / 32), split-bf16 out
    dim3 gs(SS / TN_, SS / TM_, BB);                  // 16 x 8 x 4
    mma_gemm<2><<<gs, NT, SMEM_TOTAL>>>(mQh, mQl, mKh, mKl,
                                        nullptr, Ph, Pl, nullptr,
                                        DD, SS, (size_t)SS * SS, SS, SS, 0,
                                        1.0f / 32.0f);

    // 4) row sums of exp(S)
    rowsum_kernel<<<MQKV, 256>>>(Ph, Pl, RS);

    // 5) O = (P @ V^T-rows) / rowsum
    dim3 go(DD / TN_, SS / TM_, BB);                  // 8 x 8 x 4
    mma_gemm<3><<<go, NT, SMEM_TOTAL>>>(mPh, mPl, mVh, mVl,
                                        out, nullptr, nullptr, RS,
                                        SS, DD, (size_t)SS * DD, SS, 0, SS, 1.0f);
}